// round 12
// baseline (speedup 1.0000x reference)
#include <cuda_runtime.h>
#include <cuda_bf16.h>
#include <cstdint>

// Problem dims
#define Bn 8
#define Cn 16
#define Dn 192
#define OCn 4
#define OHn 50
#define OWn 200
#define Kbig (Cn*Dn)   // 3072

typedef __nv_bfloat16 bf16;

// Scratch (fp32 device globals — verified class)
__device__ float g_Rt[Cn*Cn*Dn*Dn];                    //  Rt[i][(j,q)][n] = R[i][j][n][q]
__device__ float g_t [(size_t)Bn*Cn*Dn*Kbig];          //  t[b,i][m][(j,q)]
__device__ float g_y [(size_t)Bn*Cn*Dn*Dn];            //  y[b,i][m][n]
__device__ float g_u [(size_t)Bn*OCn*OHn*Kbig];        //  u[b,i][m][(j,q)]
__device__ float g_p [(size_t)4*Bn*OCn*OHn*OWn];       //  B2 split-K partials

// ---------------------------------------------------------------------------
// Transpose each 192x192 matrix of R (verified)
// ---------------------------------------------------------------------------
__global__ void k_transpose(const float* __restrict__ R) {
    __shared__ float tile[32][33];
    const int mat = blockIdx.z;
    const float* __restrict__ src = R    + (size_t)mat * Dn * Dn;
    float* __restrict__       dst = g_Rt + (size_t)mat * Dn * Dn;
    const int x0 = blockIdx.x * 32, y0 = blockIdx.y * 32;
    const int tx = threadIdx.x, ty = threadIdx.y;     // 32 x 8
    #pragma unroll
    for (int r = 0; r < 32; r += 8)
        tile[ty + r][tx] = src[(size_t)(y0 + ty + r) * Dn + x0 + tx];
    __syncthreads();
    #pragma unroll
    for (int r = 0; r < 32; r += 8)
        dst[(size_t)(x0 + ty + r) * Dn + y0 + tx] = tile[tx][ty + r];
}

// ---------------------------------------------------------------------------
// helpers (verified)
// ---------------------------------------------------------------------------
__device__ __forceinline__ void f2bf(float v, bf16& h, bf16& l) {
    h = __float2bfloat16_rn(v);
    l = __float2bfloat16_rn(v - __bfloat162float(h));
}
__device__ __forceinline__ void mma_bf16(float* c, const unsigned* a, const unsigned* b) {
    asm volatile(
        "mma.sync.aligned.m16n8k16.row.col.f32.bf16.bf16.f32 "
        "{%0,%1,%2,%3}, {%4,%5,%6,%7}, {%8,%9}, {%0,%1,%2,%3};\n"
        : "+f"(c[0]), "+f"(c[1]), "+f"(c[2]), "+f"(c[3])
        : "r"(a[0]), "r"(a[1]), "r"(a[2]), "r"(a[3]), "r"(b[0]), "r"(b[1]));
}
__device__ __forceinline__ void ldsm4(unsigned* r, unsigned addr) {
    asm volatile("ldmatrix.sync.aligned.m8n8.x4.shared.b16 {%0,%1,%2,%3}, [%4];\n"
                 : "=r"(r[0]), "=r"(r[1]), "=r"(r[2]), "=r"(r[3]) : "r"(addr));
}
__device__ __forceinline__ void ldsm4t(unsigned* r, unsigned addr) {
    asm volatile("ldmatrix.sync.aligned.m8n8.x4.trans.shared.b16 {%0,%1,%2,%3}, [%4];\n"
                 : "=r"(r[0]), "=r"(r[1]), "=r"(r[2]), "=r"(r[3]) : "r"(addr));
}

// ===========================================================================
// A-stage GEMM: 192x96 CTA tile, 384 threads — VERIFIED R9/R11 body.
// R12 change: callers use __launch_bounds__(384, 2) for 2 CTAs/SM.
// ===========================================================================
#define A_AP 40
#define A_BP 104

__device__ __forceinline__ void bgemmA(
    const float* __restrict__ A, int lda,
    const float* __restrict__ Bp, int ldb,
    float* __restrict__ Cp, int ldc,
    int M, int N, int K)
{
    __shared__ bf16 sA [2][192][A_AP];
    __shared__ bf16 sBh[2][16][A_BP];
    __shared__ bf16 sBl[2][16][A_BP];

    const int tid  = threadIdx.x;
    const int lane = tid & 31;
    const int warp = tid >> 5;
    const int wm = warp % 6;
    const int wn = warp / 6;
    const int row0 = 0;
    const int col0 = blockIdx.x * 96;

    const int arow = tid >> 1;
    const int ac   = (tid & 1) * 8;
    const int brow = tid / 24;
    const int bcol = (tid % 24) * 4;

    float acc[2][6][4];
    #pragma unroll
    for (int t = 0; t < 2; ++t)
        #pragma unroll
        for (int n = 0; n < 6; ++n)
            #pragma unroll
            for (int e = 0; e < 4; ++e) acc[t][n][e] = 0.f;

    unsigned aAd[2], bAdH[3], bAdL[3];
    #pragma unroll
    for (int t = 0; t < 2; ++t) {
        int rr = wm * 32 + t * 16 + (lane & 15);
        int cc = (lane >> 4) * 8;
        aAd[t] = (unsigned)__cvta_generic_to_shared(&sA[0][rr][cc]);
    }
    #pragma unroll
    for (int f = 0; f < 3; ++f) {
        int rr = lane & 15;
        int cc = wn * 48 + f * 16 + (lane >> 4) * 8;
        bAdH[f] = (unsigned)__cvta_generic_to_shared(&sBh[0][rr][cc]);
        bAdL[f] = (unsigned)__cvta_generic_to_shared(&sBl[0][rr][cc]);
    }
    const unsigned aStg = 192u * A_AP * 2u;
    const unsigned bStg = 16u * A_BP * 2u;

    float4 av[2], bv;

    auto gload = [&](int kt) {
        int gr = min(row0 + arow, M - 1);
        #pragma unroll
        for (int p = 0; p < 2; ++p)
            av[p] = *reinterpret_cast<const float4*>(&A[(size_t)gr * lda + kt + ac + p * 4]);
        int gc = min(col0 + bcol, N - 4);
        bv = *reinterpret_cast<const float4*>(&Bp[(size_t)(kt + brow) * ldb + gc]);
    };

    auto sstore = [&](int s) {
        #pragma unroll
        for (int p = 0; p < 2; ++p) {
            bf16 h0,l0,h1,l1,h2,l2,h3,l3;
            f2bf(av[p].x, h0, l0); f2bf(av[p].y, h1, l1);
            f2bf(av[p].z, h2, l2); f2bf(av[p].w, h3, l3);
            __nv_bfloat162 q;
            int c = ac + p * 4;
            q.x = h0; q.y = h1; *reinterpret_cast<__nv_bfloat162*>(&sA[s][arow][c])          = q;
            q.x = h2; q.y = h3; *reinterpret_cast<__nv_bfloat162*>(&sA[s][arow][c + 2])      = q;
            q.x = l0; q.y = l1; *reinterpret_cast<__nv_bfloat162*>(&sA[s][arow][16 + c])     = q;
            q.x = l2; q.y = l3; *reinterpret_cast<__nv_bfloat162*>(&sA[s][arow][16 + c + 2]) = q;
        }
        {
            bf16 h0,l0,h1,l1,h2,l2,h3,l3;
            f2bf(bv.x, h0, l0); f2bf(bv.y, h1, l1);
            f2bf(bv.z, h2, l2); f2bf(bv.w, h3, l3);
            __nv_bfloat162 q;
            q.x = h0; q.y = h1; *reinterpret_cast<__nv_bfloat162*>(&sBh[s][brow][bcol])     = q;
            q.x = h2; q.y = h3; *reinterpret_cast<__nv_bfloat162*>(&sBh[s][brow][bcol + 2]) = q;
            q.x = l0; q.y = l1; *reinterpret_cast<__nv_bfloat162*>(&sBl[s][brow][bcol])     = q;
            q.x = l2; q.y = l3; *reinterpret_cast<__nv_bfloat162*>(&sBl[s][brow][bcol + 2]) = q;
        }
    };

    const int niter = K / 16;
    gload(0);
    sstore(0);

    for (int it = 0; it < niter; ++it) {
        __syncthreads();
        if (it + 1 < niter) gload((it + 1) * 16);

        const int s = it & 1;
        const unsigned aOff = s * aStg, bOff = s * bStg;

        unsigned ah[2][4], al[2][4], bh[3][4], bl[3][4];
        #pragma unroll
        for (int t = 0; t < 2; ++t) {
            ldsm4(ah[t], aAd[t] + aOff);
            ldsm4(al[t], aAd[t] + aOff + 32);
        }
        #pragma unroll
        for (int f = 0; f < 3; ++f) {
            ldsm4t(bh[f], bAdH[f] + bOff);
            ldsm4t(bl[f], bAdL[f] + bOff);
        }
        #pragma unroll
        for (int t = 0; t < 2; ++t) {
            #pragma unroll
            for (int nt = 0; nt < 6; ++nt) {
                const unsigned* Bh = &bh[nt >> 1][(nt & 1) * 2];
                const unsigned* Bl = &bl[nt >> 1][(nt & 1) * 2];
                mma_bf16(acc[t][nt], ah[t], Bh);
                mma_bf16(acc[t][nt], ah[t], Bl);
                mma_bf16(acc[t][nt], al[t], Bh);
            }
        }

        if (it + 1 < niter) sstore((it + 1) & 1);
    }

    #pragma unroll
    for (int t = 0; t < 2; ++t) {
        int mB = row0 + wm * 32 + t * 16 + (lane >> 2);
        #pragma unroll
        for (int nt = 0; nt < 6; ++nt) {
            int nB = col0 + wn * 48 + nt * 8 + (lane & 3) * 2;
            float* c = acc[t][nt];
            #pragma unroll
            for (int e = 0; e < 4; ++e) {
                int gm = mB + (e >> 1) * 8;
                int gn = nB + (e & 1);
                if (gm < M && gn < N)
                    Cp[(size_t)gm * ldc + gn] = c[e];
            }
        }
    }
}

// ===========================================================================
// B-stage GEMM: 64x64 CTA tile, 128 threads — VERIFIED R11, unchanged.
// row0 FIXED at 0 (M <= 64); blockIdx.y belongs to callers.
// ===========================================================================
#define B_AP 24
#define B_BP 72

__device__ __forceinline__ void bgemmB(
    const float* __restrict__ A, int lda,
    const float* __restrict__ Bp, int ldb,
    float* __restrict__ Cp, int ldc,
    int M, int N, int K)
{
    __shared__ bf16 sAh[2][64][B_AP];
    __shared__ bf16 sAl[2][64][B_AP];
    __shared__ bf16 sBh[2][16][B_BP];
    __shared__ bf16 sBl[2][16][B_BP];

    const int tid  = threadIdx.x;
    const int lane = tid & 31;
    const int warp = tid >> 5;
    const int wm = warp & 1;
    const int wn = warp >> 1;
    const int row0 = 0;
    const int col0 = blockIdx.x * 64;

    const int ar = tid >> 1;
    const int ac = (tid & 1) * 8;
    const int br = tid >> 3;
    const int bc = (tid & 7) * 8;

    float acc[2][4][4];
    #pragma unroll
    for (int t = 0; t < 2; ++t)
        #pragma unroll
        for (int n = 0; n < 4; ++n)
            #pragma unroll
            for (int e = 0; e < 4; ++e) acc[t][n][e] = 0.f;

    unsigned aAdH[2], aAdL[2], bAdH[2], bAdL[2];
    #pragma unroll
    for (int t = 0; t < 2; ++t) {
        int rr = wm * 32 + t * 16 + (lane & 15);
        int cc = (lane >> 4) * 8;
        aAdH[t] = (unsigned)__cvta_generic_to_shared(&sAh[0][rr][cc]);
        aAdL[t] = (unsigned)__cvta_generic_to_shared(&sAl[0][rr][cc]);
    }
    #pragma unroll
    for (int p = 0; p < 2; ++p) {
        int rr = (lane & 15);
        int cc = wn * 32 + p * 16 + (lane >> 4) * 8;
        bAdH[p] = (unsigned)__cvta_generic_to_shared(&sBh[0][rr][cc]);
        bAdL[p] = (unsigned)__cvta_generic_to_shared(&sBl[0][rr][cc]);
    }
    const unsigned aStg = 64u * B_AP * 2u;
    const unsigned bStg = 16u * B_BP * 2u;

    float4 av[2], bv[2];

    auto gload = [&](int kt) {
        int gr = row0 + ar;
        #pragma unroll
        for (int p = 0; p < 2; ++p)
            av[p] = (gr < M) ? *reinterpret_cast<const float4*>(&A[(size_t)gr * lda + kt + ac + p * 4])
                             : make_float4(0.f, 0.f, 0.f, 0.f);
        #pragma unroll
        for (int p = 0; p < 2; ++p) {
            int gc = col0 + bc + p * 4;
            bv[p] = (gc < N) ? *reinterpret_cast<const float4*>(&Bp[(size_t)(kt + br) * ldb + gc])
                             : make_float4(0.f, 0.f, 0.f, 0.f);
        }
    };

    auto sstore = [&](int s) {
        #pragma unroll
        for (int p = 0; p < 2; ++p) {
            bf16 h0,l0,h1,l1,h2,l2,h3,l3;
            f2bf(av[p].x, h0, l0); f2bf(av[p].y, h1, l1);
            f2bf(av[p].z, h2, l2); f2bf(av[p].w, h3, l3);
            __nv_bfloat162 q;
            int c = ac + p * 4;
            q.x = h0; q.y = h1; *reinterpret_cast<__nv_bfloat162*>(&sAh[s][ar][c])     = q;
            q.x = h2; q.y = h3; *reinterpret_cast<__nv_bfloat162*>(&sAh[s][ar][c + 2]) = q;
            q.x = l0; q.y = l1; *reinterpret_cast<__nv_bfloat162*>(&sAl[s][ar][c])     = q;
            q.x = l2; q.y = l3; *reinterpret_cast<__nv_bfloat162*>(&sAl[s][ar][c + 2]) = q;
        }
        #pragma unroll
        for (int p = 0; p < 2; ++p) {
            bf16 h0,l0,h1,l1,h2,l2,h3,l3;
            f2bf(bv[p].x, h0, l0); f2bf(bv[p].y, h1, l1);
            f2bf(bv[p].z, h2, l2); f2bf(bv[p].w, h3, l3);
            __nv_bfloat162 q;
            int c = bc + p * 4;
            q.x = h0; q.y = h1; *reinterpret_cast<__nv_bfloat162*>(&sBh[s][br][c])     = q;
            q.x = h2; q.y = h3; *reinterpret_cast<__nv_bfloat162*>(&sBh[s][br][c + 2]) = q;
            q.x = l0; q.y = l1; *reinterpret_cast<__nv_bfloat162*>(&sBl[s][br][c])     = q;
            q.x = l2; q.y = l3; *reinterpret_cast<__nv_bfloat162*>(&sBl[s][br][c + 2]) = q;
        }
    };

    const int niter = K / 16;
    gload(0);
    sstore(0);

    for (int it = 0; it < niter; ++it) {
        __syncthreads();
        if (it + 1 < niter) gload((it + 1) * 16);

        const int s = it & 1;
        const unsigned aOff = s * aStg, bOff = s * bStg;
        unsigned ah[2][4], al[2][4], bh[2][4], bl[2][4];
        #pragma unroll
        for (int t = 0; t < 2; ++t) {
            ldsm4(ah[t], aAdH[t] + aOff);
            ldsm4(al[t], aAdL[t] + aOff);
        }
        #pragma unroll
        for (int p = 0; p < 2; ++p) {
            ldsm4t(bh[p], bAdH[p] + bOff);
            ldsm4t(bl[p], bAdL[p] + bOff);
        }
        #pragma unroll
        for (int t = 0; t < 2; ++t) {
            #pragma unroll
            for (int nt = 0; nt < 4; ++nt) {
                const unsigned* Bh = &bh[nt >> 1][(nt & 1) * 2];
                const unsigned* Bl = &bl[nt >> 1][(nt & 1) * 2];
                mma_bf16(acc[t][nt], ah[t], Bh);
                mma_bf16(acc[t][nt], ah[t], Bl);
                mma_bf16(acc[t][nt], al[t], Bh);
            }
        }

        if (it + 1 < niter) sstore((it + 1) & 1);
    }

    #pragma unroll
    for (int t = 0; t < 2; ++t) {
        int mB = row0 + wm * 32 + t * 16 + (lane >> 2);
        #pragma unroll
        for (int nt = 0; nt < 4; ++nt) {
            int nB = col0 + wn * 32 + nt * 8 + (lane & 3) * 2;
            float* c = acc[t][nt];
            #pragma unroll
            for (int e = 0; e < 4; ++e) {
                int gm = mB + (e >> 1) * 8;
                int gn = nB + (e & 1);
                if (gm < M && gn < N)
                    Cp[(size_t)gm * ldc + gn] = c[e];
            }
        }
    }
}

// ---------------------------------------------------------------------------
// Stage kernels — R12 change: A kernels get (384, 2) launch bounds
// ---------------------------------------------------------------------------
__global__ void __launch_bounds__(384, 2) k_gemm_A1(const float* __restrict__ R,
                                                    const float* __restrict__ x) {
    const int z = blockIdx.z;
    const int j = z % Cn;
    const int i = (z / Cn) % Cn;
    const int b = z / (Cn * Cn);
    const float* A  = R   + (size_t)(i * Cn + j) * Dn * Dn;
    const float* Bp = x   + (size_t)(b * Cn + j) * Dn * Dn;
    float*       Cp = g_t + (size_t)(b * Cn + i) * Dn * Kbig + (size_t)j * Dn;
    bgemmA(A, Dn, Bp, Dn, Cp, Kbig, Dn, Dn, Dn);
}

__global__ void __launch_bounds__(384, 2) k_gemm_A2() {
    const int z = blockIdx.z;                 // b*Cn + i
    const int i = z % Cn;
    const float* A  = g_t  + (size_t)z * Dn * Kbig;
    const float* Bp = g_Rt + (size_t)i * Cn * Dn * Dn;
    float*       Cp = g_y  + (size_t)z * Dn * Dn;
    bgemmA(A, Kbig, Bp, Dn, Cp, Dn, Dn, Dn, Kbig);
}

__global__ void __launch_bounds__(128) k_gemm_B1(const float* __restrict__ P) {
    const int z = blockIdx.z;                 // (b*OCn + i)*Cn + j
    const int j = z % Cn;
    const int i = (z / Cn) % OCn;
    const int b = z / (Cn * OCn);
    const float* A  = P   + (size_t)(i * Cn + j) * OHn * Dn;
    const float* Bp = g_y + (size_t)(b * Cn + j) * Dn * Dn;
    float*       Cp = g_u + (size_t)(b * OCn + i) * OHn * Kbig + (size_t)j * Dn;
    bgemmB(A, Dn, Bp, Dn, Cp, Kbig, OHn, Dn, Dn);
}

// B2 split-K: blockIdx.y = k-chunk (4 chunks of 768); writes fp32 partials.
__global__ void __launch_bounds__(128) k_gemm_B2(const float* __restrict__ PT) {
    const int z  = blockIdx.z;                // b*OCn + i
    const int ky = blockIdx.y;                // 0..3 (split-K chunk)
    const int i  = z % OCn;
    const int kt0 = ky * (Kbig / 4);          // 768
    const float* A  = g_u + (size_t)z * OHn * Kbig + kt0;
    const float* Bp = PT  + (size_t)i * (size_t)Kbig * OWn + (size_t)kt0 * OWn;
    float*       Cp = g_p + ((size_t)ky * (Bn * OCn) + z) * OHn * OWn;
    bgemmB(A, Kbig, Bp, OWn, Cp, OWn, OHn, OWn, Kbig / 4);
}

// Sum the 4 partials (fixed order -> deterministic)
__global__ void k_reduce(float* __restrict__ out) {
    const size_t n = (size_t)Bn * OCn * OHn * OWn;     // 320000
    size_t idx = (size_t)blockIdx.x * blockDim.x + threadIdx.x;
    if (idx >= n) return;
    float s = g_p[idx];
    s += g_p[n + idx];
    s += g_p[2 * n + idx];
    s += g_p[3 * n + idx];
    out[idx] = s;
}

// ---------------------------------------------------------------------------
extern "C" void kernel_launch(void* const* d_in, const int* in_sizes, int n_in,
                              void* d_out, int out_size) {
    const float* x  = (const float*)d_in[0];
    const float* R  = (const float*)d_in[1];
    const float* P  = (const float*)d_in[2];
    const float* PT = (const float*)d_in[3];
    float* out = (float*)d_out;

    k_transpose<<<dim3(6, 6, 256), dim3(32, 8)>>>(R);
    k_gemm_A1<<<dim3(2, 1, Bn * Cn * Cn), 384>>>(R, x);
    k_gemm_A2<<<dim3(2, 1, Bn * Cn), 384>>>();
    k_gemm_B1<<<dim3(3, 1, Bn * OCn * Cn), 128>>>(P);
    k_gemm_B2<<<dim3(4, 4, Bn * OCn), 128>>>(PT);
    k_reduce<<<(Bn * OCn * OHn * OWn + 255) / 256, 256>>>(out);
}

// round 13
// speedup vs baseline: 1.8115x; 1.8115x over previous
#include <cuda_runtime.h>
#include <cuda_bf16.h>
#include <cstdint>

// Problem dims
#define Bn 8
#define Cn 16
#define Dn 192
#define OCn 4
#define OHn 50
#define OWn 200
#define Kbig (Cn*Dn)   // 3072

typedef __nv_bfloat16 bf16;

// Scratch (fp32 device globals — verified class)
__device__ float g_Rt[Cn*Cn*Dn*Dn];                    //  Rt[i][(j,q)][n] = R[i][j][n][q]
__device__ float g_t [(size_t)Bn*Cn*Dn*Kbig];          //  t[b,i][m][(j,q)]
__device__ float g_y [(size_t)Bn*Cn*Dn*Dn];            //  y[b,i][m][n]
__device__ float g_u [(size_t)Bn*OCn*OHn*Kbig];        //  u[b,i][m][(j,q)]
__device__ float g_p [(size_t)4*Bn*OCn*OHn*OWn];       //  B2 split-K partials

// ---------------------------------------------------------------------------
// Transpose each 192x192 matrix of R (verified)
// ---------------------------------------------------------------------------
__global__ void k_transpose(const float* __restrict__ R) {
    __shared__ float tile[32][33];
    const int mat = blockIdx.z;
    const float* __restrict__ src = R    + (size_t)mat * Dn * Dn;
    float* __restrict__       dst = g_Rt + (size_t)mat * Dn * Dn;
    const int x0 = blockIdx.x * 32, y0 = blockIdx.y * 32;
    const int tx = threadIdx.x, ty = threadIdx.y;     // 32 x 8
    #pragma unroll
    for (int r = 0; r < 32; r += 8)
        tile[ty + r][tx] = src[(size_t)(y0 + ty + r) * Dn + x0 + tx];
    __syncthreads();
    #pragma unroll
    for (int r = 0; r < 32; r += 8)
        dst[(size_t)(x0 + ty + r) * Dn + y0 + tx] = tile[tx][ty + r];
}

// ---------------------------------------------------------------------------
// helpers (verified)
// ---------------------------------------------------------------------------
__device__ __forceinline__ void f2bf(float v, bf16& h, bf16& l) {
    h = __float2bfloat16_rn(v);
    l = __float2bfloat16_rn(v - __bfloat162float(h));
}
__device__ __forceinline__ void mma_bf16(float* c, const unsigned* a, const unsigned* b) {
    asm volatile(
        "mma.sync.aligned.m16n8k16.row.col.f32.bf16.bf16.f32 "
        "{%0,%1,%2,%3}, {%4,%5,%6,%7}, {%8,%9}, {%0,%1,%2,%3};\n"
        : "+f"(c[0]), "+f"(c[1]), "+f"(c[2]), "+f"(c[3])
        : "r"(a[0]), "r"(a[1]), "r"(a[2]), "r"(a[3]), "r"(b[0]), "r"(b[1]));
}
__device__ __forceinline__ void ldsm4(unsigned* r, unsigned addr) {
    asm volatile("ldmatrix.sync.aligned.m8n8.x4.shared.b16 {%0,%1,%2,%3}, [%4];\n"
                 : "=r"(r[0]), "=r"(r[1]), "=r"(r[2]), "=r"(r[3]) : "r"(addr));
}
__device__ __forceinline__ void ldsm4t(unsigned* r, unsigned addr) {
    asm volatile("ldmatrix.sync.aligned.m8n8.x4.trans.shared.b16 {%0,%1,%2,%3}, [%4];\n"
                 : "=r"(r[0]), "=r"(r[1]), "=r"(r[2]), "=r"(r[3]) : "r"(addr));
}

// ===========================================================================
// A-stage GEMM (R13): 192x96 CTA tile, 256 threads, 8 warps as 4m x 2n
// (48x48 warp tiles), BK=16, double-buffered, one sync/iter.
// Smem layouts IDENTICAL to verified R9/R11 (sA hi|lo interleaved, stride 40;
// sBh/sBl stride 104). 2 CTAs/SM via natural reg usage (~115 <= 128).
// Callers always have M == 192 and N == 192 (full tiles; no store guards
// strictly needed, kept for safety).
// ===========================================================================
#define A_AP 40
#define A_BP 104

__device__ __forceinline__ void bgemmA(
    const float* __restrict__ A, int lda,
    const float* __restrict__ Bp, int ldb,
    float* __restrict__ Cp, int ldc,
    int M, int N, int K)
{
    __shared__ bf16 sA [2][192][A_AP];    // 30720 B (hi cols 0-15, lo cols 16-31)
    __shared__ bf16 sBh[2][16][A_BP];     //  6656 B
    __shared__ bf16 sBl[2][16][A_BP];     //  6656 B  -> 44032 B total

    const int tid  = threadIdx.x;
    const int lane = tid & 31;
    const int warp = tid >> 5;
    const int wm = warp & 3;              // m warp 0..3 (48 rows each)
    const int wn = warp >> 2;             // n half 0..1 (48 cols each)
    const int col0 = blockIdx.x * 96;

    // gmem load mappings (256 threads)
    const int ar = tid >> 2;              // A row base 0..63 (+64p)
    const int ac = (tid & 3) * 4;         // A k col 0/4/8/12
    const int bact = tid < 192;           // B: first 192 threads
    const int br = tid / 12;              // B k-row 0..15 (for tid<192)
    const int bc = (tid % 12) * 8;        // B n-col 0..88

    float acc[3][6][4];
    #pragma unroll
    for (int t = 0; t < 3; ++t)
        #pragma unroll
        for (int n = 0; n < 6; ++n)
            #pragma unroll
            for (int e = 0; e < 4; ++e) acc[t][n][e] = 0.f;

    // ldmatrix base addresses (stage 0)
    unsigned aAd[3], bAdH[3], bAdL[3];
    #pragma unroll
    for (int t = 0; t < 3; ++t) {
        int rr = wm * 48 + t * 16 + (lane & 15);
        int cc = (lane >> 4) * 8;
        aAd[t] = (unsigned)__cvta_generic_to_shared(&sA[0][rr][cc]);
    }
    #pragma unroll
    for (int f = 0; f < 3; ++f) {
        int rr = lane & 15;
        int cc = wn * 48 + f * 16 + (lane >> 4) * 8;
        bAdH[f] = (unsigned)__cvta_generic_to_shared(&sBh[0][rr][cc]);
        bAdL[f] = (unsigned)__cvta_generic_to_shared(&sBl[0][rr][cc]);
    }
    const unsigned aStg = 192u * A_AP * 2u;
    const unsigned bStg = 16u * A_BP * 2u;

    float4 av[3], bv[2];

    auto gload = [&](int kt) {
        #pragma unroll
        for (int p = 0; p < 3; ++p) {
            int gr = min(ar + p * 64, M - 1);
            av[p] = *reinterpret_cast<const float4*>(&A[(size_t)gr * lda + kt + ac]);
        }
        if (bact) {
            int gc = min(col0 + bc, N - 8);
            size_t bo = (size_t)(kt + br) * ldb + gc;
            bv[0] = *reinterpret_cast<const float4*>(&Bp[bo]);
            bv[1] = *reinterpret_cast<const float4*>(&Bp[bo + 4]);
        }
    };

    auto sstore = [&](int s) {
        #pragma unroll
        for (int p = 0; p < 3; ++p) {
            int r = ar + p * 64;
            bf16 h0,l0,h1,l1,h2,l2,h3,l3;
            f2bf(av[p].x, h0, l0); f2bf(av[p].y, h1, l1);
            f2bf(av[p].z, h2, l2); f2bf(av[p].w, h3, l3);
            __nv_bfloat162 q;
            q.x = h0; q.y = h1; *reinterpret_cast<__nv_bfloat162*>(&sA[s][r][ac])          = q;
            q.x = h2; q.y = h3; *reinterpret_cast<__nv_bfloat162*>(&sA[s][r][ac + 2])      = q;
            q.x = l0; q.y = l1; *reinterpret_cast<__nv_bfloat162*>(&sA[s][r][16 + ac])     = q;
            q.x = l2; q.y = l3; *reinterpret_cast<__nv_bfloat162*>(&sA[s][r][16 + ac + 2]) = q;
        }
        if (bact) {
            #pragma unroll
            for (int p = 0; p < 2; ++p) {
                bf16 h0,l0,h1,l1,h2,l2,h3,l3;
                f2bf(bv[p].x, h0, l0); f2bf(bv[p].y, h1, l1);
                f2bf(bv[p].z, h2, l2); f2bf(bv[p].w, h3, l3);
                __nv_bfloat162 q;
                int c = bc + p * 4;
                q.x = h0; q.y = h1; *reinterpret_cast<__nv_bfloat162*>(&sBh[s][br][c])     = q;
                q.x = h2; q.y = h3; *reinterpret_cast<__nv_bfloat162*>(&sBh[s][br][c + 2]) = q;
                q.x = l0; q.y = l1; *reinterpret_cast<__nv_bfloat162*>(&sBl[s][br][c])     = q;
                q.x = l2; q.y = l3; *reinterpret_cast<__nv_bfloat162*>(&sBl[s][br][c + 2]) = q;
            }
        }
    };

    const int niter = K / 16;
    gload(0);
    sstore(0);

    for (int it = 0; it < niter; ++it) {
        __syncthreads();
        if (it + 1 < niter) gload((it + 1) * 16);   // hidden under MMAs

        const int s = it & 1;
        const unsigned aOff = s * aStg, bOff = s * bStg;

        unsigned ah[3][4], al[3][4], bh[3][4], bl[3][4];
        #pragma unroll
        for (int t = 0; t < 3; ++t) {
            ldsm4(ah[t], aAd[t] + aOff);            // hi at col 0
            ldsm4(al[t], aAd[t] + aOff + 32);       // lo at col 16 (+32 B)
        }
        #pragma unroll
        for (int f = 0; f < 3; ++f) {
            ldsm4t(bh[f], bAdH[f] + bOff);
            ldsm4t(bl[f], bAdL[f] + bOff);
        }
        #pragma unroll
        for (int t = 0; t < 3; ++t) {
            #pragma unroll
            for (int nt = 0; nt < 6; ++nt) {
                const unsigned* Bh = &bh[nt >> 1][(nt & 1) * 2];
                const unsigned* Bl = &bl[nt >> 1][(nt & 1) * 2];
                mma_bf16(acc[t][nt], ah[t], Bh);   // hi*hi
                mma_bf16(acc[t][nt], ah[t], Bl);   // hi*lo
                mma_bf16(acc[t][nt], al[t], Bh);   // lo*hi
            }
        }

        if (it + 1 < niter) sstore((it + 1) & 1);   // other stage; no extra sync
    }

    // epilogue (fp32)
    #pragma unroll
    for (int t = 0; t < 3; ++t) {
        int mB = wm * 48 + t * 16 + (lane >> 2);
        #pragma unroll
        for (int nt = 0; nt < 6; ++nt) {
            int nB = col0 + wn * 48 + nt * 8 + (lane & 3) * 2;
            float* c = acc[t][nt];
            #pragma unroll
            for (int e = 0; e < 4; ++e) {
                int gm = mB + (e >> 1) * 8;
                int gn = nB + (e & 1);
                if (gm < M && gn < N)
                    Cp[(size_t)gm * ldc + gn] = c[e];
            }
        }
    }
}

// ===========================================================================
// B-stage GEMM: 64x64 CTA tile, 128 threads — VERIFIED R11, unchanged.
// row0 FIXED at 0 (M <= 64); blockIdx.y belongs to callers.
// ===========================================================================
#define B_AP 24
#define B_BP 72

__device__ __forceinline__ void bgemmB(
    const float* __restrict__ A, int lda,
    const float* __restrict__ Bp, int ldb,
    float* __restrict__ Cp, int ldc,
    int M, int N, int K)
{
    __shared__ bf16 sAh[2][64][B_AP];
    __shared__ bf16 sAl[2][64][B_AP];
    __shared__ bf16 sBh[2][16][B_BP];
    __shared__ bf16 sBl[2][16][B_BP];

    const int tid  = threadIdx.x;
    const int lane = tid & 31;
    const int warp = tid >> 5;
    const int wm = warp & 1;
    const int wn = warp >> 1;
    const int row0 = 0;
    const int col0 = blockIdx.x * 64;

    const int ar = tid >> 1;
    const int ac = (tid & 1) * 8;
    const int br = tid >> 3;
    const int bc = (tid & 7) * 8;

    float acc[2][4][4];
    #pragma unroll
    for (int t = 0; t < 2; ++t)
        #pragma unroll
        for (int n = 0; n < 4; ++n)
            #pragma unroll
            for (int e = 0; e < 4; ++e) acc[t][n][e] = 0.f;

    unsigned aAdH[2], aAdL[2], bAdH[2], bAdL[2];
    #pragma unroll
    for (int t = 0; t < 2; ++t) {
        int rr = wm * 32 + t * 16 + (lane & 15);
        int cc = (lane >> 4) * 8;
        aAdH[t] = (unsigned)__cvta_generic_to_shared(&sAh[0][rr][cc]);
        aAdL[t] = (unsigned)__cvta_generic_to_shared(&sAl[0][rr][cc]);
    }
    #pragma unroll
    for (int p = 0; p < 2; ++p) {
        int rr = (lane & 15);
        int cc = wn * 32 + p * 16 + (lane >> 4) * 8;
        bAdH[p] = (unsigned)__cvta_generic_to_shared(&sBh[0][rr][cc]);
        bAdL[p] = (unsigned)__cvta_generic_to_shared(&sBl[0][rr][cc]);
    }
    const unsigned aStg = 64u * B_AP * 2u;
    const unsigned bStg = 16u * B_BP * 2u;

    float4 av[2], bv[2];

    auto gload = [&](int kt) {
        int gr = row0 + ar;
        #pragma unroll
        for (int p = 0; p < 2; ++p)
            av[p] = (gr < M) ? *reinterpret_cast<const float4*>(&A[(size_t)gr * lda + kt + ac + p * 4])
                             : make_float4(0.f, 0.f, 0.f, 0.f);
        #pragma unroll
        for (int p = 0; p < 2; ++p) {
            int gc = col0 + bc + p * 4;
            bv[p] = (gc < N) ? *reinterpret_cast<const float4*>(&Bp[(size_t)(kt + br) * ldb + gc])
                             : make_float4(0.f, 0.f, 0.f, 0.f);
        }
    };

    auto sstore = [&](int s) {
        #pragma unroll
        for (int p = 0; p < 2; ++p) {
            bf16 h0,l0,h1,l1,h2,l2,h3,l3;
            f2bf(av[p].x, h0, l0); f2bf(av[p].y, h1, l1);
            f2bf(av[p].z, h2, l2); f2bf(av[p].w, h3, l3);
            __nv_bfloat162 q;
            int c = ac + p * 4;
            q.x = h0; q.y = h1; *reinterpret_cast<__nv_bfloat162*>(&sAh[s][ar][c])     = q;
            q.x = h2; q.y = h3; *reinterpret_cast<__nv_bfloat162*>(&sAh[s][ar][c + 2]) = q;
            q.x = l0; q.y = l1; *reinterpret_cast<__nv_bfloat162*>(&sAl[s][ar][c])     = q;
            q.x = l2; q.y = l3; *reinterpret_cast<__nv_bfloat162*>(&sAl[s][ar][c + 2]) = q;
        }
        #pragma unroll
        for (int p = 0; p < 2; ++p) {
            bf16 h0,l0,h1,l1,h2,l2,h3,l3;
            f2bf(bv[p].x, h0, l0); f2bf(bv[p].y, h1, l1);
            f2bf(bv[p].z, h2, l2); f2bf(bv[p].w, h3, l3);
            __nv_bfloat162 q;
            int c = bc + p * 4;
            q.x = h0; q.y = h1; *reinterpret_cast<__nv_bfloat162*>(&sBh[s][br][c])     = q;
            q.x = h2; q.y = h3; *reinterpret_cast<__nv_bfloat162*>(&sBh[s][br][c + 2]) = q;
            q.x = l0; q.y = l1; *reinterpret_cast<__nv_bfloat162*>(&sBl[s][br][c])     = q;
            q.x = l2; q.y = l3; *reinterpret_cast<__nv_bfloat162*>(&sBl[s][br][c + 2]) = q;
        }
    };

    const int niter = K / 16;
    gload(0);
    sstore(0);

    for (int it = 0; it < niter; ++it) {
        __syncthreads();
        if (it + 1 < niter) gload((it + 1) * 16);

        const int s = it & 1;
        const unsigned aOff = s * aStg, bOff = s * bStg;
        unsigned ah[2][4], al[2][4], bh[2][4], bl[2][4];
        #pragma unroll
        for (int t = 0; t < 2; ++t) {
            ldsm4(ah[t], aAdH[t] + aOff);
            ldsm4(al[t], aAdL[t] + aOff);
        }
        #pragma unroll
        for (int p = 0; p < 2; ++p) {
            ldsm4t(bh[p], bAdH[p] + bOff);
            ldsm4t(bl[p], bAdL[p] + bOff);
        }
        #pragma unroll
        for (int t = 0; t < 2; ++t) {
            #pragma unroll
            for (int nt = 0; nt < 4; ++nt) {
                const unsigned* Bh = &bh[nt >> 1][(nt & 1) * 2];
                const unsigned* Bl = &bl[nt >> 1][(nt & 1) * 2];
                mma_bf16(acc[t][nt], ah[t], Bh);
                mma_bf16(acc[t][nt], ah[t], Bl);
                mma_bf16(acc[t][nt], al[t], Bh);
            }
        }

        if (it + 1 < niter) sstore((it + 1) & 1);
    }

    #pragma unroll
    for (int t = 0; t < 2; ++t) {
        int mB = row0 + wm * 32 + t * 16 + (lane >> 2);
        #pragma unroll
        for (int nt = 0; nt < 4; ++nt) {
            int nB = col0 + wn * 32 + nt * 8 + (lane & 3) * 2;
            float* c = acc[t][nt];
            #pragma unroll
            for (int e = 0; e < 4; ++e) {
                int gm = mB + (e >> 1) * 8;
                int gn = nB + (e & 1);
                if (gm < M && gn < N)
                    Cp[(size_t)gm * ldc + gn] = c[e];
            }
        }
    }
}

// ---------------------------------------------------------------------------
// Stage kernels — A kernels now 256 threads, (256, 2) launch bounds
// ---------------------------------------------------------------------------
__global__ void __launch_bounds__(256, 2) k_gemm_A1(const float* __restrict__ R,
                                                    const float* __restrict__ x) {
    const int z = blockIdx.z;
    const int j = z % Cn;
    const int i = (z / Cn) % Cn;
    const int b = z / (Cn * Cn);
    const float* A  = R   + (size_t)(i * Cn + j) * Dn * Dn;
    const float* Bp = x   + (size_t)(b * Cn + j) * Dn * Dn;
    float*       Cp = g_t + (size_t)(b * Cn + i) * Dn * Kbig + (size_t)j * Dn;
    bgemmA(A, Dn, Bp, Dn, Cp, Kbig, Dn, Dn, Dn);
}

__global__ void __launch_bounds__(256, 2) k_gemm_A2() {
    const int z = blockIdx.z;                 // b*Cn + i
    const int i = z % Cn;
    const float* A  = g_t  + (size_t)z * Dn * Kbig;
    const float* Bp = g_Rt + (size_t)i * Cn * Dn * Dn;
    float*       Cp = g_y  + (size_t)z * Dn * Dn;
    bgemmA(A, Kbig, Bp, Dn, Cp, Dn, Dn, Dn, Kbig);
}

__global__ void __launch_bounds__(128) k_gemm_B1(const float* __restrict__ P) {
    const int z = blockIdx.z;                 // (b*OCn + i)*Cn + j
    const int j = z % Cn;
    const int i = (z / Cn) % OCn;
    const int b = z / (Cn * OCn);
    const float* A  = P   + (size_t)(i * Cn + j) * OHn * Dn;
    const float* Bp = g_y + (size_t)(b * Cn + j) * Dn * Dn;
    float*       Cp = g_u + (size_t)(b * OCn + i) * OHn * Kbig + (size_t)j * Dn;
    bgemmB(A, Dn, Bp, Dn, Cp, Kbig, OHn, Dn, Dn);
}

// B2 split-K: blockIdx.y = k-chunk (4 chunks of 768); writes fp32 partials.
__global__ void __launch_bounds__(128) k_gemm_B2(const float* __restrict__ PT) {
    const int z  = blockIdx.z;                // b*OCn + i
    const int ky = blockIdx.y;                // 0..3 (split-K chunk)
    const int i  = z % OCn;
    const int kt0 = ky * (Kbig / 4);          // 768
    const float* A  = g_u + (size_t)z * OHn * Kbig + kt0;
    const float* Bp = PT  + (size_t)i * (size_t)Kbig * OWn + (size_t)kt0 * OWn;
    float*       Cp = g_p + ((size_t)ky * (Bn * OCn) + z) * OHn * OWn;
    bgemmB(A, Kbig, Bp, OWn, Cp, OWn, OHn, OWn, Kbig / 4);
}

// Sum the 4 partials (fixed order -> deterministic)
__global__ void k_reduce(float* __restrict__ out) {
    const size_t n = (size_t)Bn * OCn * OHn * OWn;     // 320000
    size_t idx = (size_t)blockIdx.x * blockDim.x + threadIdx.x;
    if (idx >= n) return;
    float s = g_p[idx];
    s += g_p[n + idx];
    s += g_p[2 * n + idx];
    s += g_p[3 * n + idx];
    out[idx] = s;
}

// ---------------------------------------------------------------------------
extern "C" void kernel_launch(void* const* d_in, const int* in_sizes, int n_in,
                              void* d_out, int out_size) {
    const float* x  = (const float*)d_in[0];
    const float* R  = (const float*)d_in[1];
    const float* P  = (const float*)d_in[2];
    const float* PT = (const float*)d_in[3];
    float* out = (float*)d_out;

    k_transpose<<<dim3(6, 6, 256), dim3(32, 8)>>>(R);
    k_gemm_A1<<<dim3(2, 1, Bn * Cn * Cn), 256>>>(R, x);
    k_gemm_A2<<<dim3(2, 1, Bn * Cn), 256>>>();
    k_gemm_B1<<<dim3(3, 1, Bn * OCn * Cn), 128>>>(P);
    k_gemm_B2<<<dim3(4, 4, Bn * OCn), 128>>>(PT);
    k_reduce<<<(Bn * OCn * OHn * OWn + 255) / 256, 256>>>(out);
}